// round 1
// baseline (speedup 1.0000x reference)
#include <cuda_runtime.h>
#include <math.h>

// Problem constants
#define NB 32
#define NC 256
#define NH 56
#define NW 56
#define NG 2
#define NK 7
#define NP 49          // 7*7 positions
#define CMID 64        // C/RED
#define COUT2 512      // C*G
#define NSLICE 16      // conv1 split-K slices (256/16 channels each)

// ---------------- scratch (device globals; no allocation allowed) ----------------
__device__ float g_pooled[NB * NC * NP];              // (B,C,7,7)
__device__ float g_c1part[NB * CMID * NP * NSLICE];   // conv1 split-K partials
__device__ float g_hmid[NB * CMID * NP];              // post BN+GELU
__device__ float g_logits[NB * COUT2 * NP];           // conv2 + bias
__device__ float g_dynw[NB * NC * NP];                // mixed depthwise weights

// ---------------- kernel 1: adaptive avg pool 56x56 -> 7x7 ----------------
// grid = B*C, block = 416 (392 active for row-segments, 49 for windows)
__global__ void pool_kernel(const float* __restrict__ x) {
    __shared__ float srow[392];   // [row 0..55][seg 0..6] partial 8-sums
    const int bc  = blockIdx.x;
    const int tid = threadIdx.x;
    if (tid < 392) {
        const int r = tid / 7, s = tid % 7;
        const float4* p = reinterpret_cast<const float4*>(
            x + (size_t)bc * (NH * NW) + r * NW + s * 8);
        float4 v0 = p[0], v1 = p[1];
        srow[tid] = (v0.x + v0.y + v0.z + v0.w) + (v1.x + v1.y + v1.z + v1.w);
    }
    __syncthreads();
    if (tid < NP) {
        const int wi = tid / 7, wj = tid % 7;
        float s = 0.f;
#pragma unroll
        for (int k = 0; k < 8; k++) s += srow[(wi * 8 + k) * 7 + wj];
        g_pooled[bc * NP + tid] = s * (1.0f / 64.0f);
    }
}

// ---------------- kernel 2: conv1 3x3 (256->64), split-K partials ----------------
// grid = (16 slices, 32 batches), block = 256
__global__ void conv1_kernel(const float* __restrict__ w1) {
    __shared__ float s_act[16 * 81];   // 16 ch, 9x9 zero-padded
    __shared__ float s_w[64 * 144];    // 64 oc x (16 ch * 9 taps)
    const int ks = blockIdx.x, b = blockIdx.y;
    const int tid = threadIdx.x;

    for (int idx = tid; idx < 16 * 81; idx += 256) {
        const int c = idx / 81, pp = idx % 81;
        const int gi = pp / 9 - 1, gj = pp % 9 - 1;
        float v = 0.f;
        if ((unsigned)gi < 7u && (unsigned)gj < 7u)
            v = g_pooled[(b * NC + ks * 16 + c) * NP + gi * 7 + gj];
        s_act[idx] = v;
    }
    for (int idx = tid; idx < 64 * 144; idx += 256) {
        const int oc = idx / 144, r = idx % 144;
        s_w[idx] = w1[oc * (NC * 9) + ks * 144 + r];
    }
    __syncthreads();

    const int og = tid >> 5, lane = tid & 31;
    const int p0 = lane;
    int p1 = lane + 32; if (p1 > 48) p1 = 48;
    const int ab0 = (p0 / 7) * 9 + (p0 % 7);
    const int ab1 = (p1 / 7) * 9 + (p1 % 7);
    const int OFF[9] = {0, 1, 2, 9, 10, 11, 18, 19, 20};

    float acc0[8], acc1[8];
#pragma unroll
    for (int i = 0; i < 8; i++) { acc0[i] = 0.f; acc1[i] = 0.f; }

    for (int c = 0; c < 16; c++) {
        const float* A = s_act + c * 81;
        float a0[9], a1[9];
#pragma unroll
        for (int t = 0; t < 9; t++) { a0[t] = A[ab0 + OFF[t]]; a1[t] = A[ab1 + OFF[t]]; }
#pragma unroll
        for (int i = 0; i < 8; i++) {
            const float* Wp = s_w + (og * 8 + i) * 144 + c * 9;
#pragma unroll
            for (int t = 0; t < 9; t++) {
                acc0[i] = fmaf(a0[t], Wp[t], acc0[i]);
                acc1[i] = fmaf(a1[t], Wp[t], acc1[i]);
            }
        }
    }
#pragma unroll
    for (int i = 0; i < 8; i++) {
        const int oc = og * 8 + i;
        g_c1part[((size_t)(b * CMID + oc) * NP + lane) * NSLICE + ks] = acc0[i];
        if (lane + 32 < NP)
            g_c1part[((size_t)(b * CMID + oc) * NP + lane + 32) * NSLICE + ks] = acc1[i];
    }
}

// ---------------- kernel 3: reduce partials + BN + exact GELU ----------------
// grid = 392 blocks * 256 threads = 100352 = B*64*49 exactly
__global__ void ep1_kernel(const float* __restrict__ gamma, const float* __restrict__ beta) {
    const int idx = blockIdx.x * 256 + threadIdx.x;
    const int oc = (idx / NP) & (CMID - 1);
    const float4* p = reinterpret_cast<const float4*>(g_c1part + (size_t)idx * NSLICE);
    float4 v0 = p[0], v1 = p[1], v2 = p[2], v3 = p[3];
    float s = (v0.x + v0.y + v0.z + v0.w) + (v1.x + v1.y + v1.z + v1.w)
            + (v2.x + v2.y + v2.z + v2.w) + (v3.x + v3.y + v3.z + v3.w);
    float h = s * (gamma[oc] * rsqrtf(1.0f + 1e-5f)) + beta[oc];
    // exact GELU
    g_hmid[idx] = 0.5f * h * (1.0f + erff(h * 0.70710678118654752f));
}

// ---------------- kernel 4: conv2 3x3 (64->512) + bias ----------------
// grid = (32 oc-tiles of 16, 32 batches), block = 128
__global__ void conv2_kernel(const float* __restrict__ w2, const float* __restrict__ b2) {
    __shared__ float s_act[32 * 81];   // 32 ch, 9x9 padded
    __shared__ float s_w[16 * 288];    // 16 oc x (32 ch * 9 taps)
    const int ot = blockIdx.x, b = blockIdx.y;
    const int tid = threadIdx.x;

    const int ocg = tid >> 5, lane = tid & 31;
    const int p0 = lane;
    int p1 = lane + 32; if (p1 > 48) p1 = 48;
    const int ab0 = (p0 / 7) * 9 + (p0 % 7);
    const int ab1 = (p1 / 7) * 9 + (p1 % 7);
    const int OFF[9] = {0, 1, 2, 9, 10, 11, 18, 19, 20};

    float acc0[4] = {0.f, 0.f, 0.f, 0.f};
    float acc1[4] = {0.f, 0.f, 0.f, 0.f};

    for (int ch = 0; ch < 2; ch++) {   // channel chunks of 32
        __syncthreads();
        for (int idx = tid; idx < 32 * 81; idx += 128) {
            const int c = idx / 81, pp = idx % 81;
            const int gi = pp / 9 - 1, gj = pp % 9 - 1;
            float v = 0.f;
            if ((unsigned)gi < 7u && (unsigned)gj < 7u)
                v = g_hmid[(b * CMID + ch * 32 + c) * NP + gi * 7 + gj];
            s_act[idx] = v;
        }
        for (int idx = tid; idx < 16 * 288; idx += 128) {
            const int ocl = idx / 288, r = idx % 288;
            s_w[idx] = w2[(ot * 16 + ocl) * (CMID * 9) + ch * 288 + r];
        }
        __syncthreads();

        for (int c = 0; c < 32; c++) {
            const float* A = s_act + c * 81;
            float a0[9], a1[9];
#pragma unroll
            for (int t = 0; t < 9; t++) { a0[t] = A[ab0 + OFF[t]]; a1[t] = A[ab1 + OFF[t]]; }
#pragma unroll
            for (int i = 0; i < 4; i++) {
                const float* Wp = s_w + (ocg * 4 + i) * 288 + c * 9;
#pragma unroll
                for (int t = 0; t < 9; t++) {
                    acc0[i] = fmaf(a0[t], Wp[t], acc0[i]);
                    acc1[i] = fmaf(a1[t], Wp[t], acc1[i]);
                }
            }
        }
    }
#pragma unroll
    for (int i = 0; i < 4; i++) {
        const int oc = ot * 16 + ocg * 4 + i;
        const float bias = b2[oc];
        g_logits[(size_t)(b * COUT2 + oc) * NP + lane] = acc0[i] + bias;
        if (lane + 32 < NP)
            g_logits[(size_t)(b * COUT2 + oc) * NP + lane + 32] = acc1[i] + bias;
    }
}

// ---------------- kernel 5: softmax over G=2 + mix kernel banks ----------------
// grid = 1568 * 256 = 401408 = B*C*49 exactly
__global__ void mix_kernel(const float* __restrict__ wdyn) {
    const int idx = blockIdx.x * 256 + threadIdx.x;
    const int b = idx / (NC * NP);
    const int r = idx % (NC * NP);
    const int c = r / NP, p = r % NP;
    const float l0 = g_logits[((size_t)b * COUT2 + c) * NP + p];
    const float l1 = g_logits[((size_t)b * COUT2 + NC + c) * NP + p];
    const float m = fmaxf(l0, l1);
    const float e0 = expf(l0 - m), e1 = expf(l1 - m);
    const float w0 = wdyn[c * NP + p];
    const float w1 = wdyn[NC * NP + c * NP + p];
    g_dynw[idx] = (e0 * w0 + e1 * w1) / (e0 + e1);
}

// ---------------- kernel 6: per-(b,c) depthwise 7x7 conv, pad 3 ----------------
// grid = B*C = 8192, block = 224 (4 row-groups x 56 cols); each thread: 14 rows
__global__ void dw_kernel(const float* __restrict__ x, float* __restrict__ y) {
    __shared__ float xs[62 * 62];   // 56x56 with 3-halo, zero padded
    __shared__ float ws[49];
    const int bc = blockIdx.x;
    const int tid = threadIdx.x;

    const float* xp = x + (size_t)bc * (NH * NW);
    for (int idx = tid; idx < 62 * 62; idx += 224) {
        const int r = idx / 62, cc = idx % 62;
        const int gr = r - 3, gc = cc - 3;
        float v = 0.f;
        if ((unsigned)gr < 56u && (unsigned)gc < 56u) v = xp[gr * 56 + gc];
        xs[idx] = v;
    }
    if (tid < 49) ws[tid] = g_dynw[(size_t)bc * NP + tid];
    __syncthreads();

    const int cg = tid / 56;       // row group: rows cg*14 .. cg*14+13
    const int col = tid % 56;

    float acc[14];
#pragma unroll
    for (int k = 0; k < 14; k++) acc[k] = 0.f;

    for (int dj = 0; dj < 7; dj++) {
        float cv[20];
#pragma unroll
        for (int m = 0; m < 20; m++)
            cv[m] = xs[(cg * 14 + m) * 62 + col + dj];
#pragma unroll
        for (int di = 0; di < 7; di++) {
            const float w = ws[di * 7 + dj];
#pragma unroll
            for (int k = 0; k < 14; k++)
                acc[k] = fmaf(cv[k + di], w, acc[k]);
        }
    }
    float* yp = y + (size_t)bc * (NH * NW);
#pragma unroll
    for (int k = 0; k < 14; k++)
        yp[(cg * 14 + k) * 56 + col] = acc[k];
}

// ---------------- launch ----------------
extern "C" void kernel_launch(void* const* d_in, const int* in_sizes, int n_in,
                              void* d_out, int out_size) {
    const float* x     = (const float*)d_in[0];
    const float* wdyn  = (const float*)d_in[1];
    const float* w1    = (const float*)d_in[2];
    const float* gamma = (const float*)d_in[3];
    const float* beta  = (const float*)d_in[4];
    const float* w2    = (const float*)d_in[5];
    const float* b2    = (const float*)d_in[6];
    float* y = (float*)d_out;

    pool_kernel<<<NB * NC, 416>>>(x);
    conv1_kernel<<<dim3(NSLICE, NB), 256>>>(w1);
    ep1_kernel<<<392, 256>>>(gamma, beta);
    conv2_kernel<<<dim3(32, NB), 128>>>(w2, b2);
    mix_kernel<<<1568, 256>>>(wdyn);
    dw_kernel<<<NB * NC, 224>>>(x, y);
}